// round 1
// baseline (speedup 1.0000x reference)
#include <cuda_runtime.h>
#include <math.h>

// Global scratch (no allocations allowed)
__device__ unsigned g_all[32];
__device__ unsigned g_true[32];
__device__ float    g_B[32];

// ---------------------------------------------------------------------------
// init: zero histograms, compute logit boundaries B[k] = log(k/(30-k))
// B[0] = -inf sentinel, B[30] = cutoff where float sigmoid rounds to 1.0
// ---------------------------------------------------------------------------
__global__ void init_kernel() {
    int t = threadIdx.x;
    if (t < 32) {
        g_all[t]  = 0u;
        g_true[t] = 0u;
        float b;
        if (t == 0)       b = -3.0e38f;
        else if (t < 30)  b = (float)log((double)t / (30.0 - (double)t));
        else if (t == 30) b = 17.33f;      // sigmoid_f32(x) == 1.0f beyond this
        else              b = 3.0e38f;
        g_B[t] = b;
    }
}

// ---------------------------------------------------------------------------
// Histogram kernel.
// bin(x) = #{ k in 1..30 : threshold_k <= sigmoid(x) }  computed in logit space.
// Guess j via 30*sigmoid(x) = 15*tanh(x/2)+15 with tanh.approx, quantized to
// 0.25 via magic constant 2^21 + 15.25 (floor(t+0.25±0.125) -> candidate set
// {j-1, j}), then one exact compare x >= B[j] resolves it.
// ---------------------------------------------------------------------------
#define THREADS 256

__device__ __forceinline__ void proc_elem(float x, int k, int tt, int tid,
                                          const float* sB,
                                          unsigned short* sH,
                                          unsigned* sT) {
    float r;
    asm("tanh.approx.f32 %0, %1;" : "=f"(r) : "f"(x * 0.5f));
    // y = 2^21 + q, q = (15*r + 15.25) rounded to multiple of 0.25
    float y = fmaf(r, 15.0f, 2097167.25f);   // 2^21 + 15.25 (exactly representable)
    int bits = __float_as_int(y);
    int j = (bits >> 2) & 63;                // j in [0, 30]
    float U = *(const float*)((const char*)sB + (bits & 0xFC));
    int bin = j - 1 + (x >= U);              // exact bin in [0, 30]
    // private per-thread u16 counter, conflict-free layout [bin][tid]
    unsigned short* p = &sH[bin * THREADS + tid];
    *p = (unsigned short)(*p + 1);
    if (tt == k) atomicAdd(&sT[bin], 1u);    // rare: 1 true per 64 elements
}

__global__ void __launch_bounds__(THREADS)
hist_kernel(const float4* __restrict__ in4, const int* __restrict__ target, int n4) {
    __shared__ unsigned short sH[32 * THREADS];  // 16 KB private hists
    __shared__ float sB[32];
    __shared__ unsigned sT[32];

    const int tid = threadIdx.x;
    if (tid < 32) { sB[tid] = g_B[tid]; sT[tid] = 0u; }
#pragma unroll
    for (int k = 0; k < 16; k++)
        ((unsigned*)sH)[tid + THREADS * k] = 0u;
    __syncthreads();

    const int stride = gridDim.x * THREADS;
    for (int i = blockIdx.x * THREADS + tid; i < n4; i += stride) {
        float4 v = __ldcs(in4 + i);                  // streaming: single-pass data
        int row = i >> 4;                            // 16 float4 per row (C=64)
        int tt  = __ldg(target + row) - ((i & 15) << 2);
        proc_elem(v.x, 0, tt, tid, sB, sH, sT);
        proc_elem(v.y, 1, tt, tid, sB, sH, sT);
        proc_elem(v.z, 2, tt, tid, sB, sH, sT);
        proc_elem(v.w, 3, tt, tid, sB, sH, sT);
    }
    __syncthreads();

    // Flush: 8 threads per bin, each sums 16 u32 words (32 u16 counters),
    // 3-level shuffle reduce within the 8-lane group, leader -> global atomic.
    {
        int bin = tid >> 3, part = tid & 7;
        const unsigned* rowp = (const unsigned*)(sH + bin * THREADS);
        unsigned s = 0;
#pragma unroll
        for (int w = 0; w < 16; w++) {
            unsigned v = rowp[part * 16 + w];
            s += (v & 0xFFFFu) + (v >> 16);
        }
        s += __shfl_down_sync(0xFFFFFFFFu, s, 4);
        s += __shfl_down_sync(0xFFFFFFFFu, s, 2);
        s += __shfl_down_sync(0xFFFFFFFFu, s, 1);
        if (part == 0 && s) atomicAdd(&g_all[bin], s);
    }
    if (tid < 32 && sT[tid]) atomicAdd(&g_true[tid], sT[tid]);
}

// ---------------------------------------------------------------------------
// Epilogue: replicate the reference cumsum/trapezoid math in double.
// ---------------------------------------------------------------------------
__global__ void area_kernel(float* out) {
    if (threadIdx.x != 0 || blockIdx.x != 0) return;
    double ht[31], ha[31];
    double trues = 0.0, total = 0.0;
    for (int b = 0; b < 31; b++) {
        ht[b] = (double)g_true[b];
        ha[b] = (double)g_all[b];
        trues += ht[b];
        total += ha[b];
    }
    double falses = total - trues;
    // tp_asc[i] = trues - cumsum(hist_t)[i]; reversed into descending order
    double tpr[30], fpr[30];
    double ct = 0.0, cf = 0.0;
    for (int i = 0; i < 30; i++) {
        ct += ht[i];
        cf += (ha[i] - ht[i]);
        tpr[29 - i] = (trues - ct) / (trues + 1e-8);
        fpr[29 - i] = (falses - cf) / (falses + 1e-8);
    }
    double area = 0.0, pt = 0.0, pf = 0.0;
    for (int i = 0; i < 30; i++) {
        double w = fabs(fpr[i] - pf);
        area += w * 0.5 * (tpr[i] + pt);
        pt = tpr[i];
        pf = fpr[i];
    }
    out[0] = (float)area;
}

// ---------------------------------------------------------------------------
extern "C" void kernel_launch(void* const* d_in, const int* in_sizes, int n_in,
                              void* d_out, int out_size) {
    const float* outp  = (const float*)d_in[0];
    const int* target  = (const int*)d_in[1];
    int total = in_sizes[0];     // 32,000,000
    int n4 = total / 4;

    init_kernel<<<1, 32>>>();
    int blocks = 148 * 8;        // 8 blocks/SM (16.3 KB smem each), 64 warps/SM
    hist_kernel<<<blocks, THREADS>>>((const float4*)outp, target, n4);
    area_kernel<<<1, 1>>>((float*)d_out);
}